// round 15
// baseline (speedup 1.0000x reference)
#include <cuda_runtime.h>
#include <cuda_fp16.h>
#include <cstdint>
#include <cstddef>

#define NBR 8
#define MROWS 16384
#define BN_EPS 1e-5f

// fp16 raw activation buffers
__device__ __align__(256) __half g_bufA[(size_t)NBR * MROWS * 512];
__device__ __align__(256) __half g_bufB[(size_t)NBR * MROWS * 512];
__device__ __align__(256) __half g_h4 [(size_t)NBR * MROWS * 64];
__device__ __align__(256) __half g_t1 [(size_t)NBR * MROWS * 64];
__device__ __align__(256) __half g_t2 [(size_t)NBR * MROWS * 128];
__device__ __align__(256) float  g_t3 [(size_t)NBR * MROWS * 128];
__device__ float g_psum [NBR * 512 * 128];
__device__ float g_psq  [NBR * 512 * 128];
__device__ float g_scale[6 * NBR * 512];
__device__ float g_shift[6 * NBR * 512];
// fp16 operand panels (weights + x)
__device__ __align__(16) __half g_Xf [(size_t)MROWS * 256];
__device__ __align__(16) __half g_W1f[NBR * 512 * 256];
__device__ __align__(16) __half g_W2f[NBR * 512 * 512];
__device__ __align__(16) __half g_W3f[NBR * 512 * 512];
__device__ __align__(16) __half g_W4f[NBR * 128 * 512];
__device__ __align__(16) __half g_Wa1f[NBR * 128 * 64];
__device__ __align__(16) __half g_Wa2f[NBR * 128 * 64];
__device__ __align__(16) __half g_Wa3f[NBR * 128 * 128];

__device__ __forceinline__ uint32_t smem_u32(const void* p) {
    uint32_t a;
    asm("{ .reg .u64 t; cvta.to.shared.u64 t, %1; cvt.u32.u64 %0, t; }" : "=r"(a) : "l"(p));
    return a;
}
__device__ __forceinline__ void stc_f32(uint32_t sa, uint32_t rank, float v) {
    uint32_t r;
    asm volatile("mapa.shared::cluster.u32 %0, %1, %2;" : "=r"(r) : "r"(sa), "r"(rank));
    asm volatile("st.shared::cluster.f32 [%0], %1;" :: "r"(r), "f"(v) : "memory");
}
__device__ __forceinline__ void stc_u32(uint32_t sa, uint32_t rank, uint32_t v) {
    uint32_t r;
    asm volatile("mapa.shared::cluster.u32 %0, %1, %2;" : "=r"(r) : "r"(sa), "r"(rank));
    asm volatile("st.shared::cluster.u32 [%0], %1;" :: "r"(r), "r"(v) : "memory");
}
__device__ __forceinline__ void cpa16(uint32_t d, const void* g) {
    asm volatile("cp.async.cg.shared.global [%0], [%1], 16;" :: "r"(d), "l"(g));
}
#define CP_COMMIT() asm volatile("cp.async.commit_group;")
#define CP_WAIT(N)  asm volatile("cp.async.wait_group %0;" :: "n"(N))
#define LDSM4(R, ADDR) \
    asm volatile("ldmatrix.sync.aligned.m8n8.x4.shared.b16 {%0,%1,%2,%3}, [%4];" \
        : "=r"((R)[0]), "=r"((R)[1]), "=r"((R)[2]), "=r"((R)[3]) : "r"(ADDR))
#define MMAF16(D, A, B0, B1) \
    asm volatile("mma.sync.aligned.m16n8k16.row.col.f32.f16.f16.f32 " \
        "{%0,%1,%2,%3}, {%4,%5,%6,%7}, {%8,%9}, {%0,%1,%2,%3};" \
        : "+f"((D)[0]), "+f"((D)[1]), "+f"((D)[2]), "+f"((D)[3]) \
        : "r"((A)[0]), "r"((A)[1]), "r"((A)[2]), "r"((A)[3]), "r"(B0), "r"(B1))

__device__ __forceinline__ void bnfrag(uint32_t& r, float scA, float shA, float scB, float shB) {
    __half2 h = *reinterpret_cast<__half2*>(&r);
    float f0 = fmaxf(fmaf(__half2float(h.x), scA, shA), 0.f);
    float f1 = fmaxf(fmaf(__half2float(h.y), scB, shB), 0.f);
    h.x = __float2half_rn(f0); h.y = __float2half_rn(f1);
    r = *reinterpret_cast<uint32_t*>(&h);
}

// ------------------------------ FPS (proven) --------------------------------
#define FPS_CL 4
__global__ void __cluster_dims__(FPS_CL,1,1) __launch_bounds__(512,1)
fps_kernel(const float* __restrict__ xpart, float* __restrict__ out)
{
    uint32_t rank; asm("mov.u32 %0, %%cluster_ctarank;" : "=r"(rank));
    int b = blockIdx.x / FPS_CL;
    const float* xp = xpart + (size_t)b * 32768 * 3;
    int tid = threadIdx.x, lane = tid & 31, warp = tid >> 5;
    int pbase = (int)rank * 8192;
    float px[16], py[16], pz[16], dd[16];
#pragma unroll
    for (int i = 0; i < 16; i++) {
        int p = pbase + tid + 512 * i;
        px[i] = xp[p*3]; py[i] = xp[p*3+1]; pz[i] = xp[p*3+2]; dd[i] = 1e10f;
    }
    __shared__ float wv_[16]; __shared__ int wi_[16];
    __shared__ float wx_[16], wy_[16], wz_[16];
    __shared__ float cval[2][FPS_CL]; __shared__ int cidx[2][FPS_CL];
    __shared__ float cxx[2][FPS_CL], cyy[2][FPS_CL], czz[2][FPS_CL];
    float curx = xp[0], cury = xp[1], curz = xp[2];
    float* orow = out + ((size_t)b * 2048 + 1024) * 3;
    if (rank == 0 && tid == 0) { orow[0]=curx; orow[1]=cury; orow[2]=curz; }

    for (int t = 1; t < 1024; t++) {
        float bv = -1.f; int bi = 0x7fffffff;
        float bx = 0.f, by = 0.f, bz = 0.f;
#pragma unroll
        for (int i = 0; i < 16; i++) {
            float dx = __fsub_rn(px[i], curx), dy = __fsub_rn(py[i], cury), dz = __fsub_rn(pz[i], curz);
            float d = __fadd_rn(__fadd_rn(__fmul_rn(dx,dx), __fmul_rn(dy,dy)), __fmul_rn(dz,dz));
            dd[i] = fminf(dd[i], d);
            int gi = pbase + tid + 512 * i;
            if (dd[i] > bv || (dd[i] == bv && gi < bi)) { bv=dd[i]; bi=gi; bx=px[i]; by=py[i]; bz=pz[i]; }
        }
#pragma unroll
        for (int s = 16; s > 0; s >>= 1) {
            float ov = __shfl_down_sync(0xffffffffu, bv, s);
            int   oi = __shfl_down_sync(0xffffffffu, bi, s);
            float ox = __shfl_down_sync(0xffffffffu, bx, s);
            float oy = __shfl_down_sync(0xffffffffu, by, s);
            float oz = __shfl_down_sync(0xffffffffu, bz, s);
            if (ov > bv || (ov == bv && oi < bi)) { bv=ov; bi=oi; bx=ox; by=oy; bz=oz; }
        }
        if (lane == 0) { wv_[warp]=bv; wi_[warp]=bi; wx_[warp]=bx; wy_[warp]=by; wz_[warp]=bz; }
        __syncthreads();
        int par = t & 1;
        if (warp == 0) {
            bv = (lane < 16) ? wv_[lane] : -1.f;
            bi = (lane < 16) ? wi_[lane] : 0x7fffffff;
            bx = (lane < 16) ? wx_[lane] : 0.f;
            by = (lane < 16) ? wy_[lane] : 0.f;
            bz = (lane < 16) ? wz_[lane] : 0.f;
#pragma unroll
            for (int s = 8; s > 0; s >>= 1) {
                float ov = __shfl_down_sync(0xffffffffu, bv, s);
                int   oi = __shfl_down_sync(0xffffffffu, bi, s);
                float ox = __shfl_down_sync(0xffffffffu, bx, s);
                float oy = __shfl_down_sync(0xffffffffu, by, s);
                float oz = __shfl_down_sync(0xffffffffu, bz, s);
                if (ov > bv || (ov == bv && oi < bi)) { bv=ov; bi=oi; bx=ox; by=oy; bz=oz; }
            }
            if (lane == 0) {
                for (uint32_t r = 0; r < FPS_CL; r++) {
                    stc_f32(smem_u32(&cval[par][rank]), r, bv);
                    stc_u32(smem_u32(&cidx[par][rank]), r, (uint32_t)bi);
                    stc_f32(smem_u32(&cxx[par][rank]), r, bx);
                    stc_f32(smem_u32(&cyy[par][rank]), r, by);
                    stc_f32(smem_u32(&czz[par][rank]), r, bz);
                }
            }
        }
        asm volatile("barrier.cluster.arrive.aligned;" ::: "memory");
        asm volatile("barrier.cluster.wait.aligned;" ::: "memory");
        float vv = cval[par][0]; int vi = cidx[par][0];
        float nx = cxx[par][0], ny = cyy[par][0], nz = czz[par][0];
#pragma unroll
        for (int r = 1; r < FPS_CL; r++) {
            float ov = cval[par][r]; int oi = cidx[par][r];
            if (ov > vv || (ov == vv && oi < vi)) { vv=ov; vi=oi; nx=cxx[par][r]; ny=cyy[par][r]; nz=czz[par][r]; }
        }
        curx = nx; cury = ny; curz = nz;
        if (rank == 0 && tid == 0) { orow[t*3]=nx; orow[t*3+1]=ny; orow[t*3+2]=nz; }
    }
}

// ------------------------- fp16 conversion passes ---------------------------
__global__ void conv_plain(const float* __restrict__ S, __half* __restrict__ H, int nPairs)
{
    int p = blockIdx.x * 256 + threadIdx.x;
    if (p >= nPairs) return;
    float2 v = *(const float2*)(S + (size_t)p * 2);
    __half2 h; h.x = __float2half_rn(v.x); h.y = __float2half_rn(v.y);
    *(__half2*)(H + (size_t)p * 2) = h;
}
__global__ void conv_wpad_g(const float* __restrict__ S, __half* __restrict__ H, int K, int lk)
{
    int i2 = blockIdx.x * 256 + threadIdx.x;
    int idx = i2 * 2;
    int k = idx & (K - 1), n = (idx >> lk) & 127, z = idx >> (lk + 7);
    __half2 h;
    if (n < 64) {
        float2 v = *(const float2*)(S + ((size_t)z * 64 + n) * K + k);
        h.x = __float2half_rn(v.x); h.y = __float2half_rn(v.y);
    } else {
        h.x = h.y = __float2half_rn(0.f);
    }
    *(__half2*)(H + (size_t)idx) = h;
}

// ------ fp16 tensor-core GEMM, pipelined fill-before-compute, 2 CTAs/SM ----
#define STG 20480
template<typename TOUT, bool BNA>
__global__ void __launch_bounds__(256, 2)
gemm_f16(const __half* __restrict__ Ag, const __half* __restrict__ Bg,
         TOUT* __restrict__ Call, float* __restrict__ psum, float* __restrict__ psq,
         const float* __restrict__ scg, const float* __restrict__ shg,
         int K, long aStride, long bStride, int Nout)
{
    extern __shared__ __align__(16) uint32_t sm[];
    __shared__ float s_sc[512], s_sh[512];
    int bx = blockIdx.x, by = blockIdx.y, z = blockIdx.z;
    int tid = threadIdx.x, lane = tid & 31, w = tid >> 5;
    int wm = w & 1, wn = w >> 1;
    int m0 = by * 128, n0 = bx * 128, KC = K >> 5;
    const __half* A = Ag + (size_t)z * aStride;
    const __half* B = Bg + (size_t)z * bStride;
    uint32_t sbase = smem_u32(sm);

    if (BNA) {
        for (int i = tid; i < K; i += 256) {
            s_sc[i] = scg[z * K + i];
            s_sh[i] = shg[z * K + i];
        }
    }

    int lrow = tid & 127, pan = tid >> 7;
    const __half* Grow = (pan ? B + (size_t)(n0 + lrow) * K
                              : A + (size_t)(m0 + lrow) * K);
    uint32_t drow = (uint32_t)pan * 10240 + lrow * 80;

    auto fill = [&](int kc, int s) {
        uint32_t st = sbase + s * STG + drow;
        const __half* g = Grow + kc * 32;
        cpa16(st,      g);
        cpa16(st + 16, g + 8);
        cpa16(st + 32, g + 16);
        cpa16(st + 48, g + 24);
    };

    float acc[4][4][4];
#pragma unroll
    for (int i = 0; i < 4; i++)
#pragma unroll
        for (int j = 0; j < 4; j++)
#pragma unroll
            for (int e = 0; e < 4; e++) acc[i][j][e] = 0.f;

    int pro = KC < 3 ? KC : 3;
    for (int s = 0; s < pro; s++) { fill(s, s); CP_COMMIT(); }

    int arow = lane & 15, kh = (lane >> 4) * 8;
    int bn_ = ((lane >> 4) & 1) * 8 + (lane & 7), bk = ((lane >> 3) & 1) * 8;
    int kq = (lane & 3) * 2;

    for (int kc = 0; kc < KC; kc++) {
        int s = kc & 3;
        int rem = KC - kc - 1;
        if (rem >= 2)      { CP_WAIT(2); }
        else if (rem == 1) { CP_WAIT(1); }
        else               { CP_WAIT(0); }
        __syncthreads();
        // prefetch chunk kc+3 NOW (stage (kc-1)&3 is free: all threads passed
        // this sync after finishing iteration kc-1's reads). Loads overlap MMA.
        if (kc + 3 < KC) { fill(kc + 3, (kc + 3) & 3); CP_COMMIT(); }

        uint32_t abase = sbase + s * STG + (wm * 64) * 80;
        uint32_t bbase = sbase + s * STG + 10240 + (wn * 32) * 80;
#pragma unroll
        for (int ks = 0; ks < 2; ks++) {
            uint32_t bh[2][4];
#pragma unroll
            for (int g = 0; g < 2; g++) {
                uint32_t bd = bbase + (g*16 + bn_) * 80 + (ks*16 + bk) * 2;
                LDSM4(bh[g], bd);
            }
            float sc0, sc1, sc8, sc9, sh0, sh1, sh8, sh9;
            if (BNA) {
                int k0 = kc * 32 + ks * 16 + kq;
                float2 a = *(float2*)&s_sc[k0];     sc0 = a.x; sc1 = a.y;
                float2 b = *(float2*)&s_sc[k0 + 8]; sc8 = b.x; sc9 = b.y;
                float2 c = *(float2*)&s_sh[k0];     sh0 = c.x; sh1 = c.y;
                float2 d = *(float2*)&s_sh[k0 + 8]; sh8 = d.x; sh9 = d.y;
            }
#pragma unroll
            for (int mt = 0; mt < 4; mt++) {
                uint32_t ah[4];
                uint32_t ad = abase + (mt*16 + arow) * 80 + (ks*16 + kh) * 2;
                LDSM4(ah, ad);
                if (BNA) {
                    bnfrag(ah[0], sc0, sh0, sc1, sh1);
                    bnfrag(ah[1], sc0, sh0, sc1, sh1);
                    bnfrag(ah[2], sc8, sh8, sc9, sh9);
                    bnfrag(ah[3], sc8, sh8, sc9, sh9);
                }
#pragma unroll
                for (int nt = 0; nt < 4; nt++) {
                    int g = nt >> 1, p = (nt & 1) * 2;
                    MMAF16(acc[mt][nt], ah, bh[g][p], bh[g][p+1]);
                }
            }
        }
    }
    __syncthreads();

    // epilogue: stage C in smem (pitch 132), stats + coalesced store
    float* cs = (float*)sm;
#pragma unroll
    for (int mt = 0; mt < 4; mt++)
#pragma unroll
        for (int nt = 0; nt < 4; nt++) {
            int r = wm*64 + mt*16 + (lane >> 2);
            int c = wn*32 + nt*8 + (lane & 3) * 2;
            *(float2*)(cs + r*132 + c)     = make_float2(acc[mt][nt][0], acc[mt][nt][1]);
            *(float2*)(cs + (r+8)*132 + c) = make_float2(acc[mt][nt][2], acc[mt][nt][3]);
        }
    __syncthreads();
    if (tid < 128 && n0 + tid < Nout) {
        float s = 0.f, q = 0.f;
#pragma unroll 8
        for (int r = 0; r < 128; r++) { float v = cs[r*132 + tid]; s += v; q = fmaf(v, v, q); }
        size_t ch = (size_t)z * Nout + n0 + tid;
        psum[ch * 128 + by] = s; psq[ch * 128 + by] = q;
    }
    TOUT* C = Call + (size_t)z * MROWS * Nout;
#pragma unroll
    for (int i = 0; i < 16; i++) {
        int lin = tid + 256 * i;
        int r = lin >> 5, c4 = (lin & 31) * 4;
        if (n0 + c4 < Nout) {
            float4 v = *(float4*)(cs + r*132 + c4);
            TOUT* dst = C + (size_t)(m0 + r) * Nout + n0 + c4;
            if constexpr (sizeof(TOUT) == 2) {
                __half2 h0, h1;
                h0.x = __float2half_rn(v.x); h0.y = __float2half_rn(v.y);
                h1.x = __float2half_rn(v.z); h1.y = __float2half_rn(v.w);
                uint32_t u0 = *(uint32_t*)&h0, u1 = *(uint32_t*)&h1;
                *(uint2*)dst = make_uint2(u0, u1);
            } else {
                *(float4*)dst = v;
            }
        }
    }
}

__global__ void bn_finalize(const float* __restrict__ psum, const float* __restrict__ psq,
                            const float* __restrict__ gam, const float* __restrict__ bet,
                            float* __restrict__ sc, float* __restrict__ sh, int total)
{
    int i = blockIdx.x * blockDim.x + threadIdx.x;
    if (i >= total) return;
    float s = 0.f, q = 0.f;
    const float* ps = psum + (size_t)i * 128;
    const float* pq = psq + (size_t)i * 128;
#pragma unroll 8
    for (int k = 0; k < 128; k++) { s += ps[k]; q += pq[k]; }
    float mean = s * (1.f / 16384.f);
    float var = fmaf(-mean, mean, q * (1.f / 16384.f));
    float g = gam[i] * rsqrtf(var + BN_EPS);
    sc[i] = g; sh[i] = fmaf(-mean, g, bet[i]);
}

// ----------------------------- softmax/pool ---------------------------------
__global__ void __launch_bounds__(256, 1)
softmax_pts_kernel(const float* __restrict__ t3, const __half* __restrict__ h4raw,
                   const float* __restrict__ scaleL, const float* __restrict__ shiftL,
                   const float* __restrict__ aW4, const float* __restrict__ ab4,
                   float* __restrict__ out)
{
    int b = blockIdx.x, n = blockIdx.y;
    extern __shared__ float base_sh[];
    __shared__ float w4[3][64], b4[3];
    int tid = threadIdx.x;
    if (tid < 192) w4[tid / 64][tid % 64] = aW4[n * 192 + tid];
    if (tid < 3) b4[tid] = ab4[n * 3 + tid];
    const float* sc = scaleL + n * 64;
    const float* sh = shiftL + n * 64;
    const __half* h4b = h4raw + ((size_t)n * MROWS + b * 512) * 64;
    for (int i = tid; i < 512 * 64; i += 256) {
        int l = i >> 6, k = i & 63;
        base_sh[l * 65 + k] = fmaxf(fmaf(__half2float(h4b[i]), sc[k], sh[k]), 0.f);
    }
    __syncthreads();
    int lane = tid & 31, warp = tid >> 5;
    const float* t3b = t3 + ((size_t)n * MROWS + b * 512) * 128;
    float* orow = out + ((size_t)b * 2048 + n * 128) * 3;
    for (int c = 0; c < 16; c++) {
        int m = warp + c * 8;
        float v[16], mx = -1e30f;
#pragma unroll
        for (int i = 0; i < 16; i++) { v[i] = t3b[(size_t)(lane + 32*i) * 128 + m]; mx = fmaxf(mx, v[i]); }
#pragma unroll
        for (int s = 16; s > 0; s >>= 1) mx = fmaxf(mx, __shfl_xor_sync(0xffffffffu, mx, s));
        float sum = 0.f;
#pragma unroll
        for (int i = 0; i < 16; i++) { v[i] = expf(v[i] - mx); sum += v[i]; }
#pragma unroll
        for (int s = 16; s > 0; s >>= 1) sum += __shfl_xor_sync(0xffffffffu, sum, s);
        float inv = 1.f / sum;
#pragma unroll
        for (int i = 0; i < 16; i++) v[i] *= inv;
        float o0 = 0.f, o1 = 0.f, o2 = 0.f;
        for (int k = 0; k < 64; k++) {
            float p = 0.f;
#pragma unroll
            for (int i = 0; i < 16; i++) p = fmaf(v[i], base_sh[(lane + 32*i) * 65 + k], p);
#pragma unroll
            for (int s = 16; s > 0; s >>= 1) p += __shfl_xor_sync(0xffffffffu, p, s);
            o0 = fmaf(w4[0][k], p, o0); o1 = fmaf(w4[1][k], p, o1); o2 = fmaf(w4[2][k], p, o2);
        }
        if (lane == 0) { orow[m*3] = o0 + b4[0]; orow[m*3+1] = o1 + b4[1]; orow[m*3+2] = o2 + b4[2]; }
    }
}

// ------------------------------- launch ------------------------------------
extern "C" void kernel_launch(void* const* d_in, const int* in_sizes, int n_in,
                              void* d_out, int out_size)
{
    (void)in_sizes; (void)n_in; (void)out_size;
    const float* x     = (const float*)d_in[0];
    const float* xpart = (const float*)d_in[1];
    const float* mW1 = (const float*)d_in[2];
    const float* mg1 = (const float*)d_in[4];
    const float* mB1 = (const float*)d_in[5];
    const float* mW2 = (const float*)d_in[6];
    const float* mg2 = (const float*)d_in[8];
    const float* mB2 = (const float*)d_in[9];
    const float* mW3 = (const float*)d_in[10];
    const float* mg3 = (const float*)d_in[12];
    const float* mB3 = (const float*)d_in[13];
    const float* mW4 = (const float*)d_in[14];
    const float* mg4 = (const float*)d_in[16];
    const float* mB4 = (const float*)d_in[17];
    const float* aW1 = (const float*)d_in[18];
    const float* ag1 = (const float*)d_in[20];
    const float* aB1 = (const float*)d_in[21];
    const float* aW2 = (const float*)d_in[22];
    const float* ag2 = (const float*)d_in[24];
    const float* aB2 = (const float*)d_in[25];
    const float* aW3 = (const float*)d_in[26];
    const float* aW4 = (const float*)d_in[28];
    const float* ab4 = (const float*)d_in[29];
    float* out = (float*)d_out;

    __half *bufA, *bufB, *h4, *t1, *t2;
    float *t3, *psum, *psq, *sc, *sh;
    __half *Xf, *W1f, *W2f, *W3f, *W4f, *Wa1f, *Wa2f, *Wa3f;
    cudaGetSymbolAddress((void**)&bufA, g_bufA);
    cudaGetSymbolAddress((void**)&bufB, g_bufB);
    cudaGetSymbolAddress((void**)&h4, g_h4);
    cudaGetSymbolAddress((void**)&t1, g_t1);
    cudaGetSymbolAddress((void**)&t2, g_t2);
    cudaGetSymbolAddress((void**)&t3, g_t3);
    cudaGetSymbolAddress((void**)&psum, g_psum);
    cudaGetSymbolAddress((void**)&psq, g_psq);
    cudaGetSymbolAddress((void**)&sc, g_scale);
    cudaGetSymbolAddress((void**)&sh, g_shift);
    cudaGetSymbolAddress((void**)&Xf, g_Xf);
    cudaGetSymbolAddress((void**)&W1f, g_W1f);
    cudaGetSymbolAddress((void**)&W2f, g_W2f);
    cudaGetSymbolAddress((void**)&W3f, g_W3f);
    cudaGetSymbolAddress((void**)&W4f, g_W4f);
    cudaGetSymbolAddress((void**)&Wa1f, g_Wa1f);
    cudaGetSymbolAddress((void**)&Wa2f, g_Wa2f);
    cudaGetSymbolAddress((void**)&Wa3f, g_Wa3f);

    static bool init_done = false;
    static cudaStream_t s2;
    static cudaEvent_t evFork, evJoin;
    if (!init_done) {
        cudaFuncSetAttribute(softmax_pts_kernel, cudaFuncAttributeMaxDynamicSharedMemorySize, 512 * 65 * 4);
        cudaFuncSetAttribute(gemm_f16<__half, false>, cudaFuncAttributeMaxDynamicSharedMemorySize, 81920);
        cudaFuncSetAttribute(gemm_f16<__half, true>,  cudaFuncAttributeMaxDynamicSharedMemorySize, 81920);
        cudaFuncSetAttribute(gemm_f16<float, true>,   cudaFuncAttributeMaxDynamicSharedMemorySize, 81920);
        cudaStreamCreateWithFlags(&s2, cudaStreamNonBlocking);
        cudaEventCreateWithFlags(&evFork, cudaEventDisableTiming);
        cudaEventCreateWithFlags(&evJoin, cudaEventDisableTiming);
        init_done = true;
    }

    const int SL = NBR * 512;
    const long MS512 = (long)MROWS * 512;
    const long MS64  = (long)MROWS * 64;
    const long MS128 = (long)MROWS * 128;

    cudaEventRecord(evFork, 0);
    cudaStreamWaitEvent(s2, evFork, 0);
    fps_kernel<<<32 * FPS_CL, 512, 0, s2>>>(xpart, out);
    cudaEventRecord(evJoin, s2);

    conv_plain<<<(NBR*512*128)/256, 256>>>(mW1, W1f, NBR*512*128);
    conv_plain<<<(NBR*512*256)/256, 256>>>(mW2, W2f, NBR*512*256);
    conv_plain<<<(NBR*512*256)/256, 256>>>(mW3, W3f, NBR*512*256);
    conv_wpad_g<<<(NBR*128*512)/512, 256>>>(mW4, W4f, 512, 9);
    conv_wpad_g<<<(NBR*128*64)/512, 256>>>(aW1, Wa1f, 64, 6);
    conv_plain<<<(NBR*128*32)/256, 256>>>(aW2, Wa2f, NBR*128*32);
    conv_plain<<<(NBR*128*64)/256, 256>>>(aW3, Wa3f, NBR*128*64);
    conv_plain<<<(MROWS*128)/256, 256>>>(x, Xf, MROWS*128);

    gemm_f16<__half, false><<<dim3(4, 128, NBR), 256, 81920>>>(
        Xf, W1f, bufA, psum, psq, nullptr, nullptr, 256, 0, 512L*256, 512);
    bn_finalize<<<16, 256>>>(psum, psq, mg1, mB1, sc, sh, NBR * 512);

    gemm_f16<__half, true><<<dim3(4, 128, NBR), 256, 81920>>>(
        bufA, W2f, bufB, psum, psq, sc, sh, 512, MS512, 512L*512, 512);
    bn_finalize<<<16, 256>>>(psum, psq, mg2, mB2, sc + SL, sh + SL, NBR * 512);

    gemm_f16<__half, true><<<dim3(4, 128, NBR), 256, 81920>>>(
        bufB, W3f, bufA, psum, psq, sc + SL, sh + SL, 512, MS512, 512L*512, 512);
    bn_finalize<<<16, 256>>>(psum, psq, mg3, mB3, sc + 2 * SL, sh + 2 * SL, NBR * 512);

    gemm_f16<__half, true><<<dim3(1, 128, NBR), 256, 81920>>>(
        bufA, W4f, h4, psum, psq, sc + 2 * SL, sh + 2 * SL, 512, MS512, 128L*512, 64);
    bn_finalize<<<2, 256>>>(psum, psq, mg4, mB4, sc + 3 * SL, sh + 3 * SL, NBR * 64);

    gemm_f16<__half, true><<<dim3(1, 128, NBR), 256, 81920>>>(
        h4, Wa1f, t1, psum, psq, sc + 3 * SL, sh + 3 * SL, 64, MS64, 128L*64, 64);
    bn_finalize<<<2, 256>>>(psum, psq, ag1, aB1, sc + 4 * SL, sh + 4 * SL, NBR * 64);

    gemm_f16<__half, true><<<dim3(1, 128, NBR), 256, 81920>>>(
        t1, Wa2f, t2, psum, psq, sc + 4 * SL, sh + 4 * SL, 64, MS64, 128L*64, 128);
    bn_finalize<<<4, 256>>>(psum, psq, ag2, aB2, sc + 5 * SL, sh + 5 * SL, NBR * 128);

    gemm_f16<float, true><<<dim3(1, 128, NBR), 256, 81920>>>(
        t2, Wa3f, t3, psum, psq, sc + 5 * SL, sh + 5 * SL, 128, MS128, 128L*128, 128);

    softmax_pts_kernel<<<dim3(32, NBR), 256, 512 * 65 * 4>>>(
        t3, h4, sc + 3 * SL, sh + 3 * SL, aW4, ab4, out);

    cudaStreamWaitEvent(0, evJoin, 0);
}

// round 16
// speedup vs baseline: 1.0443x; 1.0443x over previous
#include <cuda_runtime.h>
#include <cuda_fp16.h>
#include <cstdint>
#include <cstddef>

#define NBR 8
#define MROWS 16384
#define BN_EPS 1e-5f

// fp16 raw activation buffers
__device__ __align__(256) __half g_bufA[(size_t)NBR * MROWS * 512];
__device__ __align__(256) __half g_bufB[(size_t)NBR * MROWS * 512];
__device__ __align__(256) __half g_h4 [(size_t)NBR * MROWS * 64];
__device__ __align__(256) __half g_t1 [(size_t)NBR * MROWS * 64];
__device__ __align__(256) __half g_t2 [(size_t)NBR * MROWS * 128];
__device__ __align__(256) float  g_t3 [(size_t)NBR * MROWS * 128];
__device__ float g_psum [NBR * 512 * 128];
__device__ float g_psq  [NBR * 512 * 128];
__device__ float g_scale[6 * NBR * 512];
__device__ float g_shift[6 * NBR * 512];
// fp16 operand panels (weights + x)
__device__ __align__(16) __half g_Xf [(size_t)MROWS * 256];
__device__ __align__(16) __half g_W1f[NBR * 512 * 256];
__device__ __align__(16) __half g_W2f[NBR * 512 * 512];
__device__ __align__(16) __half g_W3f[NBR * 512 * 512];
__device__ __align__(16) __half g_W4f[NBR * 128 * 512];
__device__ __align__(16) __half g_Wa1f[NBR * 128 * 64];
__device__ __align__(16) __half g_Wa2f[NBR * 128 * 64];
__device__ __align__(16) __half g_Wa3f[NBR * 128 * 128];

__device__ __forceinline__ uint32_t smem_u32(const void* p) {
    uint32_t a;
    asm("{ .reg .u64 t; cvta.to.shared.u64 t, %1; cvt.u32.u64 %0, t; }" : "=r"(a) : "l"(p));
    return a;
}
__device__ __forceinline__ void stc_f32(uint32_t sa, uint32_t rank, float v) {
    uint32_t r;
    asm volatile("mapa.shared::cluster.u32 %0, %1, %2;" : "=r"(r) : "r"(sa), "r"(rank));
    asm volatile("st.shared::cluster.f32 [%0], %1;" :: "r"(r), "f"(v) : "memory");
}
__device__ __forceinline__ void stc_u32(uint32_t sa, uint32_t rank, uint32_t v) {
    uint32_t r;
    asm volatile("mapa.shared::cluster.u32 %0, %1, %2;" : "=r"(r) : "r"(sa), "r"(rank));
    asm volatile("st.shared::cluster.u32 [%0], %1;" :: "r"(r), "r"(v) : "memory");
}
__device__ __forceinline__ void cpa16(uint32_t d, const void* g) {
    asm volatile("cp.async.cg.shared.global [%0], [%1], 16;" :: "r"(d), "l"(g));
}
#define CP_COMMIT() asm volatile("cp.async.commit_group;")
#define CP_WAIT(N)  asm volatile("cp.async.wait_group %0;" :: "n"(N))
#define LDSM4(R, ADDR) \
    asm volatile("ldmatrix.sync.aligned.m8n8.x4.shared.b16 {%0,%1,%2,%3}, [%4];" \
        : "=r"((R)[0]), "=r"((R)[1]), "=r"((R)[2]), "=r"((R)[3]) : "r"(ADDR))
#define MMAF16(D, A, B0, B1) \
    asm volatile("mma.sync.aligned.m16n8k16.row.col.f32.f16.f16.f32 " \
        "{%0,%1,%2,%3}, {%4,%5,%6,%7}, {%8,%9}, {%0,%1,%2,%3};" \
        : "+f"((D)[0]), "+f"((D)[1]), "+f"((D)[2]), "+f"((D)[3]) \
        : "r"((A)[0]), "r"((A)[1]), "r"((A)[2]), "r"((A)[3]), "r"(B0), "r"(B1))

// BN+ReLU on a packed half2 fragment register: 1 hfma2 + 1 hmax2
__device__ __forceinline__ void bnfrag2(uint32_t& r, uint32_t sc2, uint32_t sh2) {
    __half2 h = *reinterpret_cast<__half2*>(&r);
    __half2 s = *reinterpret_cast<__half2*>(&sc2);
    __half2 t = *reinterpret_cast<__half2*>(&sh2);
    __half2 v = __hmax2(__hfma2(h, s, t), __half2half2(__ushort_as_half(0)));
    r = *reinterpret_cast<uint32_t*>(&v);
}

// ------------------------------ FPS (proven) --------------------------------
#define FPS_CL 4
__global__ void __cluster_dims__(FPS_CL,1,1) __launch_bounds__(512,1)
fps_kernel(const float* __restrict__ xpart, float* __restrict__ out)
{
    uint32_t rank; asm("mov.u32 %0, %%cluster_ctarank;" : "=r"(rank));
    int b = blockIdx.x / FPS_CL;
    const float* xp = xpart + (size_t)b * 32768 * 3;
    int tid = threadIdx.x, lane = tid & 31, warp = tid >> 5;
    int pbase = (int)rank * 8192;
    float px[16], py[16], pz[16], dd[16];
#pragma unroll
    for (int i = 0; i < 16; i++) {
        int p = pbase + tid + 512 * i;
        px[i] = xp[p*3]; py[i] = xp[p*3+1]; pz[i] = xp[p*3+2]; dd[i] = 1e10f;
    }
    __shared__ float wv_[16]; __shared__ int wi_[16];
    __shared__ float wx_[16], wy_[16], wz_[16];
    __shared__ float cval[2][FPS_CL]; __shared__ int cidx[2][FPS_CL];
    __shared__ float cxx[2][FPS_CL], cyy[2][FPS_CL], czz[2][FPS_CL];
    float curx = xp[0], cury = xp[1], curz = xp[2];
    float* orow = out + ((size_t)b * 2048 + 1024) * 3;
    if (rank == 0 && tid == 0) { orow[0]=curx; orow[1]=cury; orow[2]=curz; }

    for (int t = 1; t < 1024; t++) {
        float bv = -1.f; int bi = 0x7fffffff;
        float bx = 0.f, by = 0.f, bz = 0.f;
#pragma unroll
        for (int i = 0; i < 16; i++) {
            float dx = __fsub_rn(px[i], curx), dy = __fsub_rn(py[i], cury), dz = __fsub_rn(pz[i], curz);
            float d = __fadd_rn(__fadd_rn(__fmul_rn(dx,dx), __fmul_rn(dy,dy)), __fmul_rn(dz,dz));
            dd[i] = fminf(dd[i], d);
            int gi = pbase + tid + 512 * i;
            if (dd[i] > bv || (dd[i] == bv && gi < bi)) { bv=dd[i]; bi=gi; bx=px[i]; by=py[i]; bz=pz[i]; }
        }
#pragma unroll
        for (int s = 16; s > 0; s >>= 1) {
            float ov = __shfl_down_sync(0xffffffffu, bv, s);
            int   oi = __shfl_down_sync(0xffffffffu, bi, s);
            float ox = __shfl_down_sync(0xffffffffu, bx, s);
            float oy = __shfl_down_sync(0xffffffffu, by, s);
            float oz = __shfl_down_sync(0xffffffffu, bz, s);
            if (ov > bv || (ov == bv && oi < bi)) { bv=ov; bi=oi; bx=ox; by=oy; bz=oz; }
        }
        if (lane == 0) { wv_[warp]=bv; wi_[warp]=bi; wx_[warp]=bx; wy_[warp]=by; wz_[warp]=bz; }
        __syncthreads();
        int par = t & 1;
        if (warp == 0) {
            bv = (lane < 16) ? wv_[lane] : -1.f;
            bi = (lane < 16) ? wi_[lane] : 0x7fffffff;
            bx = (lane < 16) ? wx_[lane] : 0.f;
            by = (lane < 16) ? wy_[lane] : 0.f;
            bz = (lane < 16) ? wz_[lane] : 0.f;
#pragma unroll
            for (int s = 8; s > 0; s >>= 1) {
                float ov = __shfl_down_sync(0xffffffffu, bv, s);
                int   oi = __shfl_down_sync(0xffffffffu, bi, s);
                float ox = __shfl_down_sync(0xffffffffu, bx, s);
                float oy = __shfl_down_sync(0xffffffffu, by, s);
                float oz = __shfl_down_sync(0xffffffffu, bz, s);
                if (ov > bv || (ov == bv && oi < bi)) { bv=ov; bi=oi; bx=ox; by=oy; bz=oz; }
            }
            if (lane == 0) {
                for (uint32_t r = 0; r < FPS_CL; r++) {
                    stc_f32(smem_u32(&cval[par][rank]), r, bv);
                    stc_u32(smem_u32(&cidx[par][rank]), r, (uint32_t)bi);
                    stc_f32(smem_u32(&cxx[par][rank]), r, bx);
                    stc_f32(smem_u32(&cyy[par][rank]), r, by);
                    stc_f32(smem_u32(&czz[par][rank]), r, bz);
                }
            }
        }
        asm volatile("barrier.cluster.arrive.aligned;" ::: "memory");
        asm volatile("barrier.cluster.wait.aligned;" ::: "memory");
        float vv = cval[par][0]; int vi = cidx[par][0];
        float nx = cxx[par][0], ny = cyy[par][0], nz = czz[par][0];
#pragma unroll
        for (int r = 1; r < FPS_CL; r++) {
            float ov = cval[par][r]; int oi = cidx[par][r];
            if (ov > vv || (ov == vv && oi < vi)) { vv=ov; vi=oi; nx=cxx[par][r]; ny=cyy[par][r]; nz=czz[par][r]; }
        }
        curx = nx; cury = ny; curz = nz;
        if (rank == 0 && tid == 0) { orow[t*3]=nx; orow[t*3+1]=ny; orow[t*3+2]=nz; }
    }
}

// ------------------------- fp16 conversion passes ---------------------------
__global__ void conv_plain(const float* __restrict__ S, __half* __restrict__ H, int nPairs)
{
    int p = blockIdx.x * 256 + threadIdx.x;
    if (p >= nPairs) return;
    float2 v = *(const float2*)(S + (size_t)p * 2);
    __half2 h; h.x = __float2half_rn(v.x); h.y = __float2half_rn(v.y);
    *(__half2*)(H + (size_t)p * 2) = h;
}
__global__ void conv_wpad_g(const float* __restrict__ S, __half* __restrict__ H, int K, int lk)
{
    int i2 = blockIdx.x * 256 + threadIdx.x;
    int idx = i2 * 2;
    int k = idx & (K - 1), n = (idx >> lk) & 127, z = idx >> (lk + 7);
    __half2 h;
    if (n < 64) {
        float2 v = *(const float2*)(S + ((size_t)z * 64 + n) * K + k);
        h.x = __float2half_rn(v.x); h.y = __float2half_rn(v.y);
    } else {
        h.x = h.y = __float2half_rn(0.f);
    }
    *(__half2*)(H + (size_t)idx) = h;
}

// ------ fp16 tensor-core GEMM, pipelined, half2 fused BN on A --------------
#define STG 20480
template<typename TOUT, bool BNA>
__global__ void __launch_bounds__(256, 2)
gemm_f16(const __half* __restrict__ Ag, const __half* __restrict__ Bg,
         TOUT* __restrict__ Call, float* __restrict__ psum, float* __restrict__ psq,
         const float* __restrict__ scg, const float* __restrict__ shg,
         int K, long aStride, long bStride, int Nout)
{
    extern __shared__ __align__(16) uint32_t sm[];
    __shared__ uint32_t s_sc2[256], s_sh2[256];    // packed half2 per channel pair
    int bx = blockIdx.x, by = blockIdx.y, z = blockIdx.z;
    int tid = threadIdx.x, lane = tid & 31, w = tid >> 5;
    int wm = w & 1, wn = w >> 1;
    int m0 = by * 128, n0 = bx * 128, KC = K >> 5;
    const __half* A = Ag + (size_t)z * aStride;
    const __half* B = Bg + (size_t)z * bStride;
    uint32_t sbase = smem_u32(sm);

    if (BNA) {
        for (int i = tid; i < (K >> 1); i += 256) {
            float2 s = *(const float2*)(scg + z * K + i * 2);
            float2 t = *(const float2*)(shg + z * K + i * 2);
            __half2 hs; hs.x = __float2half_rn(s.x); hs.y = __float2half_rn(s.y);
            __half2 ht; ht.x = __float2half_rn(t.x); ht.y = __float2half_rn(t.y);
            s_sc2[i] = *reinterpret_cast<uint32_t*>(&hs);
            s_sh2[i] = *reinterpret_cast<uint32_t*>(&ht);
        }
    }

    int lrow = tid & 127, pan = tid >> 7;
    const __half* Grow = (pan ? B + (size_t)(n0 + lrow) * K
                              : A + (size_t)(m0 + lrow) * K);
    uint32_t drow = (uint32_t)pan * 10240 + lrow * 80;

    auto fill = [&](int kc, int s) {
        uint32_t st = sbase + s * STG + drow;
        const __half* g = Grow + kc * 32;
        cpa16(st,      g);
        cpa16(st + 16, g + 8);
        cpa16(st + 32, g + 16);
        cpa16(st + 48, g + 24);
    };

    float acc[4][4][4];
#pragma unroll
    for (int i = 0; i < 4; i++)
#pragma unroll
        for (int j = 0; j < 4; j++)
#pragma unroll
            for (int e = 0; e < 4; e++) acc[i][j][e] = 0.f;

    int pro = KC < 3 ? KC : 3;
    for (int s = 0; s < pro; s++) { fill(s, s); CP_COMMIT(); }

    int arow = lane & 15, kh = (lane >> 4) * 8;
    int bn_ = ((lane >> 4) & 1) * 8 + (lane & 7), bk = ((lane >> 3) & 1) * 8;
    int kq = (lane & 3);   // half2 pair index within 8-wide group

    for (int kc = 0; kc < KC; kc++) {
        int s = kc & 3;
        int rem = KC - kc - 1;
        if (rem >= 2)      { CP_WAIT(2); }
        else if (rem == 1) { CP_WAIT(1); }
        else               { CP_WAIT(0); }
        __syncthreads();
        if (kc + 3 < KC) { fill(kc + 3, (kc + 3) & 3); CP_COMMIT(); }

        uint32_t abase = sbase + s * STG + (wm * 64) * 80;
        uint32_t bbase = sbase + s * STG + 10240 + (wn * 32) * 80;
#pragma unroll
        for (int ks = 0; ks < 2; ks++) {
            uint32_t bh[2][4];
#pragma unroll
            for (int g = 0; g < 2; g++) {
                uint32_t bd = bbase + (g*16 + bn_) * 80 + (ks*16 + bk) * 2;
                LDSM4(bh[g], bd);
            }
            uint32_t sc2a, sc2b, sh2a, sh2b;
            if (BNA) {
                int i0 = kc * 16 + ks * 8 + kq;     // channel-pair index
                sc2a = s_sc2[i0];     sh2a = s_sh2[i0];
                sc2b = s_sc2[i0 + 4]; sh2b = s_sh2[i0 + 4];
            }
#pragma unroll
            for (int mt = 0; mt < 4; mt++) {
                uint32_t ah[4];
                uint32_t ad = abase + (mt*16 + arow) * 80 + (ks*16 + kh) * 2;
                LDSM4(ah, ad);
                if (BNA) {
                    bnfrag2(ah[0], sc2a, sh2a);
                    bnfrag2(ah[1], sc2a, sh2a);
                    bnfrag2(ah[2], sc2b, sh2b);
                    bnfrag2(ah[3], sc2b, sh2b);
                }
#pragma unroll
                for (int nt = 0; nt < 4; nt++) {
                    int g = nt >> 1, p = (nt & 1) * 2;
                    MMAF16(acc[mt][nt], ah, bh[g][p], bh[g][p+1]);
                }
            }
        }
    }
    __syncthreads();

    // epilogue: stage C in smem (pitch 132), stats + coalesced store
    float* cs = (float*)sm;
#pragma unroll
    for (int mt = 0; mt < 4; mt++)
#pragma unroll
        for (int nt = 0; nt < 4; nt++) {
            int r = wm*64 + mt*16 + (lane >> 2);
            int c = wn*32 + nt*8 + (lane & 3) * 2;
            *(float2*)(cs + r*132 + c)     = make_float2(acc[mt][nt][0], acc[mt][nt][1]);
            *(float2*)(cs + (r+8)*132 + c) = make_float2(acc[mt][nt][2], acc[mt][nt][3]);
        }
    __syncthreads();
    if (tid < 128 && n0 + tid < Nout) {
        float s = 0.f, q = 0.f;
#pragma unroll 8
        for (int r = 0; r < 128; r++) { float v = cs[r*132 + tid]; s += v; q = fmaf(v, v, q); }
        size_t ch = (size_t)z * Nout + n0 + tid;
        psum[ch * 128 + by] = s; psq[ch * 128 + by] = q;
    }
    TOUT* C = Call + (size_t)z * MROWS * Nout;
#pragma unroll
    for (int i = 0; i < 16; i++) {
        int lin = tid + 256 * i;
        int r = lin >> 5, c4 = (lin & 31) * 4;
        if (n0 + c4 < Nout) {
            float4 v = *(float4*)(cs + r*132 + c4);
            TOUT* dst = C + (size_t)(m0 + r) * Nout + n0 + c4;
            if constexpr (sizeof(TOUT) == 2) {
                __half2 h0, h1;
                h0.x = __float2half_rn(v.x); h0.y = __float2half_rn(v.y);
                h1.x = __float2half_rn(v.z); h1.y = __float2half_rn(v.w);
                uint32_t u0 = *(uint32_t*)&h0, u1 = *(uint32_t*)&h1;
                *(uint2*)dst = make_uint2(u0, u1);
            } else {
                *(float4*)dst = v;
            }
        }
    }
}

__global__ void bn_finalize(const float* __restrict__ psum, const float* __restrict__ psq,
                            const float* __restrict__ gam, const float* __restrict__ bet,
                            float* __restrict__ sc, float* __restrict__ sh, int total)
{
    int i = blockIdx.x * blockDim.x + threadIdx.x;
    if (i >= total) return;
    float s = 0.f, q = 0.f;
    const float* ps = psum + (size_t)i * 128;
    const float* pq = psq + (size_t)i * 128;
#pragma unroll 8
    for (int k = 0; k < 128; k++) { s += ps[k]; q += pq[k]; }
    float mean = s * (1.f / 16384.f);
    float var = fmaf(-mean, mean, q * (1.f / 16384.f));
    float g = gam[i] * rsqrtf(var + BN_EPS);
    sc[i] = g; sh[i] = fmaf(-mean, g, bet[i]);
}

// ----------------------------- softmax/pool ---------------------------------
__global__ void __launch_bounds__(256, 1)
softmax_pts_kernel(const float* __restrict__ t3, const __half* __restrict__ h4raw,
                   const float* __restrict__ scaleL, const float* __restrict__ shiftL,
                   const float* __restrict__ aW4, const float* __restrict__ ab4,
                   float* __restrict__ out)
{
    int b = blockIdx.x, n = blockIdx.y;
    extern __shared__ float base_sh[];
    __shared__ float w4[3][64], b4[3];
    int tid = threadIdx.x;
    if (tid < 192) w4[tid / 64][tid % 64] = aW4[n * 192 + tid];
    if (tid < 3) b4[tid] = ab4[n * 3 + tid];
    const float* sc = scaleL + n * 64;
    const float* sh = shiftL + n * 64;
    const __half* h4b = h4raw + ((size_t)n * MROWS + b * 512) * 64;
    for (int i = tid; i < 512 * 64; i += 256) {
        int l = i >> 6, k = i & 63;
        base_sh[l * 65 + k] = fmaxf(fmaf(__half2float(h4b[i]), sc[k], sh[k]), 0.f);
    }
    __syncthreads();
    int lane = tid & 31, warp = tid >> 5;
    const float* t3b = t3 + ((size_t)n * MROWS + b * 512) * 128;
    float* orow = out + ((size_t)b * 2048 + n * 128) * 3;
    for (int c = 0; c < 16; c++) {
        int m = warp + c * 8;
        float v[16], mx = -1e30f;
#pragma unroll
        for (int i = 0; i < 16; i++) { v[i] = t3b[(size_t)(lane + 32*i) * 128 + m]; mx = fmaxf(mx, v[i]); }
#pragma unroll
        for (int s = 16; s > 0; s >>= 1) mx = fmaxf(mx, __shfl_xor_sync(0xffffffffu, mx, s));
        float sum = 0.f;
#pragma unroll
        for (int i = 0; i < 16; i++) { v[i] = expf(v[i] - mx); sum += v[i]; }
#pragma unroll
        for (int s = 16; s > 0; s >>= 1) sum += __shfl_xor_sync(0xffffffffu, sum, s);
        float inv = 1.f / sum;
#pragma unroll
        for (int i = 0; i < 16; i++) v[i] *= inv;
        float o0 = 0.f, o1 = 0.f, o2 = 0.f;
        for (int k = 0; k < 64; k++) {
            float p = 0.f;
#pragma unroll
            for (int i = 0; i < 16; i++) p = fmaf(v[i], base_sh[(lane + 32*i) * 65 + k], p);
#pragma unroll
            for (int s = 16; s > 0; s >>= 1) p += __shfl_xor_sync(0xffffffffu, p, s);
            o0 = fmaf(w4[0][k], p, o0); o1 = fmaf(w4[1][k], p, o1); o2 = fmaf(w4[2][k], p, o2);
        }
        if (lane == 0) { orow[m*3] = o0 + b4[0]; orow[m*3+1] = o1 + b4[1]; orow[m*3+2] = o2 + b4[2]; }
    }
}

// ------------------------------- launch ------------------------------------
extern "C" void kernel_launch(void* const* d_in, const int* in_sizes, int n_in,
                              void* d_out, int out_size)
{
    (void)in_sizes; (void)n_in; (void)out_size;
    const float* x     = (const float*)d_in[0];
    const float* xpart = (const float*)d_in[1];
    const float* mW1 = (const float*)d_in[2];
    const float* mg1 = (const float*)d_in[4];
    const float* mB1 = (const float*)d_in[5];
    const float* mW2 = (const float*)d_in[6];
    const float* mg2 = (const float*)d_in[8];
    const float* mB2 = (const float*)d_in[9];
    const float* mW3 = (const float*)d_in[10];
    const float* mg3 = (const float*)d_in[12];
    const float* mB3 = (const float*)d_in[13];
    const float* mW4 = (const float*)d_in[14];
    const float* mg4 = (const float*)d_in[16];
    const float* mB4 = (const float*)d_in[17];
    const float* aW1 = (const float*)d_in[18];
    const float* ag1 = (const float*)d_in[20];
    const float* aB1 = (const float*)d_in[21];
    const float* aW2 = (const float*)d_in[22];
    const float* ag2 = (const float*)d_in[24];
    const float* aB2 = (const float*)d_in[25];
    const float* aW3 = (const float*)d_in[26];
    const float* aW4 = (const float*)d_in[28];
    const float* ab4 = (const float*)d_in[29];
    float* out = (float*)d_out;

    __half *bufA, *bufB, *h4, *t1, *t2;
    float *t3, *psum, *psq, *sc, *sh;
    __half *Xf, *W1f, *W2f, *W3f, *W4f, *Wa1f, *Wa2f, *Wa3f;
    cudaGetSymbolAddress((void**)&bufA, g_bufA);
    cudaGetSymbolAddress((void**)&bufB, g_bufB);
    cudaGetSymbolAddress((void**)&h4, g_h4);
    cudaGetSymbolAddress((void**)&t1, g_t1);
    cudaGetSymbolAddress((void**)&t2, g_t2);
    cudaGetSymbolAddress((void**)&t3, g_t3);
    cudaGetSymbolAddress((void**)&psum, g_psum);
    cudaGetSymbolAddress((void**)&psq, g_psq);
    cudaGetSymbolAddress((void**)&sc, g_scale);
    cudaGetSymbolAddress((void**)&sh, g_shift);
    cudaGetSymbolAddress((void**)&Xf, g_Xf);
    cudaGetSymbolAddress((void**)&W1f, g_W1f);
    cudaGetSymbolAddress((void**)&W2f, g_W2f);
    cudaGetSymbolAddress((void**)&W3f, g_W3f);
    cudaGetSymbolAddress((void**)&W4f, g_W4f);
    cudaGetSymbolAddress((void**)&Wa1f, g_Wa1f);
    cudaGetSymbolAddress((void**)&Wa2f, g_Wa2f);
    cudaGetSymbolAddress((void**)&Wa3f, g_Wa3f);

    static bool init_done = false;
    static cudaStream_t s2;
    static cudaEvent_t evFork, evJoin;
    if (!init_done) {
        cudaFuncSetAttribute(softmax_pts_kernel, cudaFuncAttributeMaxDynamicSharedMemorySize, 512 * 65 * 4);
        cudaFuncSetAttribute(gemm_f16<__half, false>, cudaFuncAttributeMaxDynamicSharedMemorySize, 81920);
        cudaFuncSetAttribute(gemm_f16<__half, true>,  cudaFuncAttributeMaxDynamicSharedMemorySize, 81920);
        cudaFuncSetAttribute(gemm_f16<float, true>,   cudaFuncAttributeMaxDynamicSharedMemorySize, 81920);
        cudaStreamCreateWithFlags(&s2, cudaStreamNonBlocking);
        cudaEventCreateWithFlags(&evFork, cudaEventDisableTiming);
        cudaEventCreateWithFlags(&evJoin, cudaEventDisableTiming);
        init_done = true;
    }

    const int SL = NBR * 512;
    const long MS512 = (long)MROWS * 512;
    const long MS64  = (long)MROWS * 64;
    const long MS128 = (long)MROWS * 128;

    cudaEventRecord(evFork, 0);
    cudaStreamWaitEvent(s2, evFork, 0);
    fps_kernel<<<32 * FPS_CL, 512, 0, s2>>>(xpart, out);
    cudaEventRecord(evJoin, s2);

    conv_plain<<<(NBR*512*128)/256, 256>>>(mW1, W1f, NBR*512*128);
    conv_plain<<<(NBR*512*256)/256, 256>>>(mW2, W2f, NBR*512*256);
    conv_plain<<<(NBR*512*256)/256, 256>>>(mW3, W3f, NBR*512*256);
    conv_wpad_g<<<(NBR*128*512)/512, 256>>>(mW4, W4f, 512, 9);
    conv_wpad_g<<<(NBR*128*64)/512, 256>>>(aW1, Wa1f, 64, 6);
    conv_plain<<<(NBR*128*32)/256, 256>>>(aW2, Wa2f, NBR*128*32);
    conv_plain<<<(NBR*128*64)/256, 256>>>(aW3, Wa3f, NBR*128*64);
    conv_plain<<<(MROWS*128)/256, 256>>>(x, Xf, MROWS*128);

    gemm_f16<__half, false><<<dim3(4, 128, NBR), 256, 81920>>>(
        Xf, W1f, bufA, psum, psq, nullptr, nullptr, 256, 0, 512L*256, 512);
    bn_finalize<<<16, 256>>>(psum, psq, mg1, mB1, sc, sh, NBR * 512);

    gemm_f16<__half, true><<<dim3(4, 128, NBR), 256, 81920>>>(
        bufA, W2f, bufB, psum, psq, sc, sh, 512, MS512, 512L*512, 512);
    bn_finalize<<<16, 256>>>(psum, psq, mg2, mB2, sc + SL, sh + SL, NBR * 512);

    gemm_f16<__half, true><<<dim3(4, 128, NBR), 256, 81920>>>(
        bufB, W3f, bufA, psum, psq, sc + SL, sh + SL, 512, MS512, 512L*512, 512);
    bn_finalize<<<16, 256>>>(psum, psq, mg3, mB3, sc + 2 * SL, sh + 2 * SL, NBR * 512);

    gemm_f16<__half, true><<<dim3(1, 128, NBR), 256, 81920>>>(
        bufA, W4f, h4, psum, psq, sc + 2 * SL, sh + 2 * SL, 512, MS512, 128L*512, 64);
    bn_finalize<<<2, 256>>>(psum, psq, mg4, mB4, sc + 3 * SL, sh + 3 * SL, NBR * 64);

    gemm_f16<__half, true><<<dim3(1, 128, NBR), 256, 81920>>>(
        h4, Wa1f, t1, psum, psq, sc + 3 * SL, sh + 3 * SL, 64, MS64, 128L*64, 64);
    bn_finalize<<<2, 256>>>(psum, psq, ag1, aB1, sc + 4 * SL, sh + 4 * SL, NBR * 64);

    gemm_f16<__half, true><<<dim3(1, 128, NBR), 256, 81920>>>(
        t1, Wa2f, t2, psum, psq, sc + 4 * SL, sh + 4 * SL, 64, MS64, 128L*64, 128);
    bn_finalize<<<4, 256>>>(psum, psq, ag2, aB2, sc + 5 * SL, sh + 5 * SL, NBR * 128);

    gemm_f16<float, true><<<dim3(1, 128, NBR), 256, 81920>>>(
        t2, Wa3f, t3, psum, psq, sc + 5 * SL, sh + 5 * SL, 128, MS128, 128L*128, 128);

    softmax_pts_kernel<<<dim3(32, NBR), 256, 512 * 65 * 4>>>(
        t3, h4, sc + 3 * SL, sh + 3 * SL, aW4, ab4, out);

    cudaStreamWaitEvent(0, evJoin, 0);
}

// round 17
// speedup vs baseline: 1.0478x; 1.0034x over previous
#include <cuda_runtime.h>
#include <cuda_fp16.h>
#include <cstdint>
#include <cstddef>

#define NBR 8
#define MROWS 16384
#define BN_EPS 1e-5f

__device__ __align__(256) __half g_bufA[(size_t)NBR * MROWS * 512];
__device__ __align__(256) __half g_bufB[(size_t)NBR * MROWS * 512];
__device__ __align__(256) __half g_h4 [(size_t)NBR * MROWS * 64];
__device__ __align__(256) __half g_t1 [(size_t)NBR * MROWS * 64];
__device__ __align__(256) __half g_t2 [(size_t)NBR * MROWS * 128];
__device__ __align__(256) float  g_t3 [(size_t)NBR * MROWS * 128];
__device__ float g_psum [NBR * 512 * 128];
__device__ float g_psq  [NBR * 512 * 128];
__device__ float g_scale[6 * NBR * 512];
__device__ float g_shift[6 * NBR * 512];
__device__ __align__(16) __half g_Xf [(size_t)MROWS * 256];
__device__ __align__(16) __half g_W1f[NBR * 512 * 256];
__device__ __align__(16) __half g_W2f[NBR * 512 * 512];
__device__ __align__(16) __half g_W3f[NBR * 512 * 512];
__device__ __align__(16) __half g_W4f[NBR * 128 * 512];
__device__ __align__(16) __half g_Wa1f[NBR * 128 * 64];
__device__ __align__(16) __half g_Wa2f[NBR * 128 * 64];
__device__ __align__(16) __half g_Wa3f[NBR * 128 * 128];

__device__ __forceinline__ uint32_t smem_u32(const void* p) {
    uint32_t a;
    asm("{ .reg .u64 t; cvta.to.shared.u64 t, %1; cvt.u32.u64 %0, t; }" : "=r"(a) : "l"(p));
    return a;
}
__device__ __forceinline__ void stc_f32(uint32_t sa, uint32_t rank, float v) {
    uint32_t r;
    asm volatile("mapa.shared::cluster.u32 %0, %1, %2;" : "=r"(r) : "r"(sa), "r"(rank));
    asm volatile("st.shared::cluster.f32 [%0], %1;" :: "r"(r), "f"(v) : "memory");
}
__device__ __forceinline__ void stc_u32(uint32_t sa, uint32_t rank, uint32_t v) {
    uint32_t r;
    asm volatile("mapa.shared::cluster.u32 %0, %1, %2;" : "=r"(r) : "r"(sa), "r"(rank));
    asm volatile("st.shared::cluster.u32 [%0], %1;" :: "r"(r), "r"(v) : "memory");
}
__device__ __forceinline__ void cpa16(uint32_t d, const void* g) {
    asm volatile("cp.async.cg.shared.global [%0], [%1], 16;" :: "r"(d), "l"(g));
}
#define CP_COMMIT() asm volatile("cp.async.commit_group;")
#define CP_WAIT(N)  asm volatile("cp.async.wait_group %0;" :: "n"(N))
#define LDSM4(R, ADDR) \
    asm volatile("ldmatrix.sync.aligned.m8n8.x4.shared.b16 {%0,%1,%2,%3}, [%4];" \
        : "=r"((R)[0]), "=r"((R)[1]), "=r"((R)[2]), "=r"((R)[3]) : "r"(ADDR))
#define MMAF16(D, A, B0, B1) \
    asm volatile("mma.sync.aligned.m16n8k16.row.col.f32.f16.f16.f32 " \
        "{%0,%1,%2,%3}, {%4,%5,%6,%7}, {%8,%9}, {%0,%1,%2,%3};" \
        : "+f"((D)[0]), "+f"((D)[1]), "+f"((D)[2]), "+f"((D)[3]) \
        : "r"((A)[0]), "r"((A)[1]), "r"((A)[2]), "r"((A)[3]), "r"(B0), "r"(B1))

__device__ __forceinline__ void bnfrag2(uint32_t& r, uint32_t sc2, uint32_t sh2) {
    __half2 h = *reinterpret_cast<__half2*>(&r);
    __half2 s = *reinterpret_cast<__half2*>(&sc2);
    __half2 t = *reinterpret_cast<__half2*>(&sh2);
    __half2 v = __hmax2(__hfma2(h, s, t), __half2half2(__ushort_as_half(0)));
    r = *reinterpret_cast<uint32_t*>(&v);
}

// ------------------------------ FPS (proven) --------------------------------
#define FPS_CL 4
__global__ void __cluster_dims__(FPS_CL,1,1) __launch_bounds__(512,1)
fps_kernel(const float* __restrict__ xpart, float* __restrict__ out)
{
    uint32_t rank; asm("mov.u32 %0, %%cluster_ctarank;" : "=r"(rank));
    int b = blockIdx.x / FPS_CL;
    const float* xp = xpart + (size_t)b * 32768 * 3;
    int tid = threadIdx.x, lane = tid & 31, warp = tid >> 5;
    int pbase = (int)rank * 8192;
    float px[16], py[16], pz[16], dd[16];
#pragma unroll
    for (int i = 0; i < 16; i++) {
        int p = pbase + tid + 512 * i;
        px[i] = xp[p*3]; py[i] = xp[p*3+1]; pz[i] = xp[p*3+2]; dd[i] = 1e10f;
    }
    __shared__ float wv_[16]; __shared__ int wi_[16];
    __shared__ float wx_[16], wy_[16], wz_[16];
    __shared__ float cval[2][FPS_CL]; __shared__ int cidx[2][FPS_CL];
    __shared__ float cxx[2][FPS_CL], cyy[2][FPS_CL], czz[2][FPS_CL];
    float curx = xp[0], cury = xp[1], curz = xp[2];
    float* orow = out + ((size_t)b * 2048 + 1024) * 3;
    if (rank == 0 && tid == 0) { orow[0]=curx; orow[1]=cury; orow[2]=curz; }

    for (int t = 1; t < 1024; t++) {
        float bv = -1.f; int bi = 0x7fffffff;
        float bx = 0.f, by = 0.f, bz = 0.f;
#pragma unroll
        for (int i = 0; i < 16; i++) {
            float dx = __fsub_rn(px[i], curx), dy = __fsub_rn(py[i], cury), dz = __fsub_rn(pz[i], curz);
            float d = __fadd_rn(__fadd_rn(__fmul_rn(dx,dx), __fmul_rn(dy,dy)), __fmul_rn(dz,dz));
            dd[i] = fminf(dd[i], d);
            int gi = pbase + tid + 512 * i;
            if (dd[i] > bv || (dd[i] == bv && gi < bi)) { bv=dd[i]; bi=gi; bx=px[i]; by=py[i]; bz=pz[i]; }
        }
#pragma unroll
        for (int s = 16; s > 0; s >>= 1) {
            float ov = __shfl_down_sync(0xffffffffu, bv, s);
            int   oi = __shfl_down_sync(0xffffffffu, bi, s);
            float ox = __shfl_down_sync(0xffffffffu, bx, s);
            float oy = __shfl_down_sync(0xffffffffu, by, s);
            float oz = __shfl_down_sync(0xffffffffu, bz, s);
            if (ov > bv || (ov == bv && oi < bi)) { bv=ov; bi=oi; bx=ox; by=oy; bz=oz; }
        }
        if (lane == 0) { wv_[warp]=bv; wi_[warp]=bi; wx_[warp]=bx; wy_[warp]=by; wz_[warp]=bz; }
        __syncthreads();
        int par = t & 1;
        if (warp == 0) {
            bv = (lane < 16) ? wv_[lane] : -1.f;
            bi = (lane < 16) ? wi_[lane] : 0x7fffffff;
            bx = (lane < 16) ? wx_[lane] : 0.f;
            by = (lane < 16) ? wy_[lane] : 0.f;
            bz = (lane < 16) ? wz_[lane] : 0.f;
#pragma unroll
            for (int s = 8; s > 0; s >>= 1) {
                float ov = __shfl_down_sync(0xffffffffu, bv, s);
                int   oi = __shfl_down_sync(0xffffffffu, bi, s);
                float ox = __shfl_down_sync(0xffffffffu, bx, s);
                float oy = __shfl_down_sync(0xffffffffu, by, s);
                float oz = __shfl_down_sync(0xffffffffu, bz, s);
                if (ov > bv || (ov == bv && oi < bi)) { bv=ov; bi=oi; bx=ox; by=oy; bz=oz; }
            }
            if (lane == 0) {
                for (uint32_t r = 0; r < FPS_CL; r++) {
                    stc_f32(smem_u32(&cval[par][rank]), r, bv);
                    stc_u32(smem_u32(&cidx[par][rank]), r, (uint32_t)bi);
                    stc_f32(smem_u32(&cxx[par][rank]), r, bx);
                    stc_f32(smem_u32(&cyy[par][rank]), r, by);
                    stc_f32(smem_u32(&czz[par][rank]), r, bz);
                }
            }
        }
        asm volatile("barrier.cluster.arrive.aligned;" ::: "memory");
        asm volatile("barrier.cluster.wait.aligned;" ::: "memory");
        float vv = cval[par][0]; int vi = cidx[par][0];
        float nx = cxx[par][0], ny = cyy[par][0], nz = czz[par][0];
#pragma unroll
        for (int r = 1; r < FPS_CL; r++) {
            float ov = cval[par][r]; int oi = cidx[par][r];
            if (ov > vv || (ov == vv && oi < vi)) { vv=ov; vi=oi; nx=cxx[par][r]; ny=cyy[par][r]; nz=czz[par][r]; }
        }
        curx = nx; cury = ny; curz = nz;
        if (rank == 0 && tid == 0) { orow[t*3]=nx; orow[t*3+1]=ny; orow[t*3+2]=nz; }
    }
}

// ------------------------- fp16 conversion passes ---------------------------
__global__ void conv_plain(const float* __restrict__ S, __half* __restrict__ H, int nPairs)
{
    int p = blockIdx.x * 256 + threadIdx.x;
    if (p >= nPairs) return;
    float2 v = *(const float2*)(S + (size_t)p * 2);
    __half2 h; h.x = __float2half_rn(v.x); h.y = __float2half_rn(v.y);
    *(__half2*)(H + (size_t)p * 2) = h;
}
__global__ void conv_wpad_g(const float* __restrict__ S, __half* __restrict__ H, int K, int lk)
{
    int i2 = blockIdx.x * 256 + threadIdx.x;
    int idx = i2 * 2;
    int k = idx & (K - 1), n = (idx >> lk) & 127, z = idx >> (lk + 7);
    __half2 h;
    if (n < 64) {
        float2 v = *(const float2*)(S + ((size_t)z * 64 + n) * K + k);
        h.x = __float2half_rn(v.x); h.y = __float2half_rn(v.y);
    } else {
        h.x = h.y = __float2half_rn(0.f);
    }
    *(__half2*)(H + (size_t)idx) = h;
}

// --- fp16 tensor-core GEMM, K-chunk 64, 3-stage pipeline, fused BN on A ----
// stage: A 128 rows x 64 half (pitch 144B) = 18432B, B same at +18432
#define STG 36864
template<typename TOUT, bool BNA>
__global__ void __launch_bounds__(256, 2)
gemm_f16(const __half* __restrict__ Ag, const __half* __restrict__ Bg,
         TOUT* __restrict__ Call, float* __restrict__ psum, float* __restrict__ psq,
         const float* __restrict__ scg, const float* __restrict__ shg,
         int K, long aStride, long bStride, int Nout)
{
    extern __shared__ __align__(16) uint32_t sm[];
    __shared__ uint32_t s_sc2[256], s_sh2[256];
    int bx = blockIdx.x, by = blockIdx.y, z = blockIdx.z;
    int tid = threadIdx.x, lane = tid & 31, w = tid >> 5;
    int wm = w & 1, wn = w >> 1;
    int m0 = by * 128, n0 = bx * 128, KC = K >> 6;
    const __half* A = Ag + (size_t)z * aStride;
    const __half* B = Bg + (size_t)z * bStride;
    uint32_t sbase = smem_u32(sm);

    if (BNA) {
        for (int i = tid; i < (K >> 1); i += 256) {
            float2 s = *(const float2*)(scg + z * K + i * 2);
            float2 t = *(const float2*)(shg + z * K + i * 2);
            __half2 hs; hs.x = __float2half_rn(s.x); hs.y = __float2half_rn(s.y);
            __half2 ht; ht.x = __float2half_rn(t.x); ht.y = __float2half_rn(t.y);
            s_sc2[i] = *reinterpret_cast<uint32_t*>(&hs);
            s_sh2[i] = *reinterpret_cast<uint32_t*>(&ht);
        }
    }

    // loader: 1 thread per row of 64 halfs (128B = 8x16B)
    int lrow = tid & 127, pan = tid >> 7;
    const __half* Grow = (pan ? B + (size_t)(n0 + lrow) * K
                              : A + (size_t)(m0 + lrow) * K);
    uint32_t drow = (uint32_t)pan * 18432 + lrow * 144;

    auto fill = [&](int kc, int s) {
        uint32_t st = sbase + s * STG + drow;
        const __half* g = Grow + kc * 64;
#pragma unroll
        for (int i = 0; i < 8; i++) cpa16(st + i * 16, g + i * 8);
    };

    float acc[4][4][4];
#pragma unroll
    for (int i = 0; i < 4; i++)
#pragma unroll
        for (int j = 0; j < 4; j++)
#pragma unroll
            for (int e = 0; e < 4; e++) acc[i][j][e] = 0.f;

    int pro = KC < 2 ? KC : 2;
    for (int s = 0; s < pro; s++) { fill(s, s); CP_COMMIT(); }

    int arow = lane & 15, kh = (lane >> 4) * 8;
    int bn_ = ((lane >> 4) & 1) * 8 + (lane & 7), bk = ((lane >> 3) & 1) * 8;
    int kq = (lane & 3);

    int s = 0;
    for (int kc = 0; kc < KC; kc++) {
        int rem = KC - kc - 1;
        if (rem >= 1) { CP_WAIT(1); } else { CP_WAIT(0); }
        __syncthreads();
        // prefetch chunk kc+2 into stage (s+2)%3 (free since last iteration)
        if (kc + 2 < KC) {
            int ps = (s >= 1) ? s - 1 : s + 2;
            fill(kc + 2, ps); CP_COMMIT();
        }

        uint32_t abase = sbase + s * STG + (wm * 64) * 144;
        uint32_t bbase = sbase + s * STG + 18432 + (wn * 32) * 144;
#pragma unroll
        for (int ks = 0; ks < 4; ks++) {
            uint32_t bh[2][4];
#pragma unroll
            for (int g = 0; g < 2; g++) {
                uint32_t bd = bbase + (g*16 + bn_) * 144 + (ks*16 + bk) * 2;
                LDSM4(bh[g], bd);
            }
            uint32_t sc2a, sc2b, sh2a, sh2b;
            if (BNA) {
                int i0 = kc * 32 + ks * 8 + kq;
                sc2a = s_sc2[i0];     sh2a = s_sh2[i0];
                sc2b = s_sc2[i0 + 4]; sh2b = s_sh2[i0 + 4];
            }
#pragma unroll
            for (int mt = 0; mt < 4; mt++) {
                uint32_t ah[4];
                uint32_t ad = abase + (mt*16 + arow) * 144 + (ks*16 + kh) * 2;
                LDSM4(ah, ad);
                if (BNA) {
                    bnfrag2(ah[0], sc2a, sh2a);
                    bnfrag2(ah[1], sc2a, sh2a);
                    bnfrag2(ah[2], sc2b, sh2b);
                    bnfrag2(ah[3], sc2b, sh2b);
                }
#pragma unroll
                for (int nt = 0; nt < 4; nt++) {
                    int g = nt >> 1, p = (nt & 1) * 2;
                    MMAF16(acc[mt][nt], ah, bh[g][p], bh[g][p+1]);
                }
            }
        }
        s = (s == 2) ? 0 : s + 1;
    }
    __syncthreads();

    // epilogue: stage C in smem (pitch 132), stats + coalesced store
    float* cs = (float*)sm;
#pragma unroll
    for (int mt = 0; mt < 4; mt++)
#pragma unroll
        for (int nt = 0; nt < 4; nt++) {
            int r = wm*64 + mt*16 + (lane >> 2);
            int c = wn*32 + nt*8 + (lane & 3) * 2;
            *(float2*)(cs + r*132 + c)     = make_float2(acc[mt][nt][0], acc[mt][nt][1]);
            *(float2*)(cs + (r+8)*132 + c) = make_float2(acc[mt][nt][2], acc[mt][nt][3]);
        }
    __syncthreads();
    if (tid < 128 && n0 + tid < Nout) {
        float sgm = 0.f, q = 0.f;
#pragma unroll 8
        for (int r = 0; r < 128; r++) { float v = cs[r*132 + tid]; sgm += v; q = fmaf(v, v, q); }
        size_t ch = (size_t)z * Nout + n0 + tid;
        psum[ch * 128 + by] = sgm; psq[ch * 128 + by] = q;
    }
    TOUT* C = Call + (size_t)z * MROWS * Nout;
#pragma unroll
    for (int i = 0; i < 16; i++) {
        int lin = tid + 256 * i;
        int r = lin >> 5, c4 = (lin & 31) * 4;
        if (n0 + c4 < Nout) {
            float4 v = *(float4*)(cs + r*132 + c4);
            TOUT* dst = C + (size_t)(m0 + r) * Nout + n0 + c4;
            if constexpr (sizeof(TOUT) == 2) {
                __half2 h0, h1;
                h0.x = __float2half_rn(v.x); h0.y = __float2half_rn(v.y);
                h1.x = __float2half_rn(v.z); h1.y = __float2half_rn(v.w);
                uint32_t u0 = *(uint32_t*)&h0, u1 = *(uint32_t*)&h1;
                *(uint2*)dst = make_uint2(u0, u1);
            } else {
                *(float4*)dst = v;
            }
        }
    }
}

__global__ void bn_finalize(const float* __restrict__ psum, const float* __restrict__ psq,
                            const float* __restrict__ gam, const float* __restrict__ bet,
                            float* __restrict__ sc, float* __restrict__ sh, int total)
{
    int i = blockIdx.x * blockDim.x + threadIdx.x;
    if (i >= total) return;
    float s = 0.f, q = 0.f;
    const float* ps = psum + (size_t)i * 128;
    const float* pq = psq + (size_t)i * 128;
#pragma unroll 8
    for (int k = 0; k < 128; k++) { s += ps[k]; q += pq[k]; }
    float mean = s * (1.f / 16384.f);
    float var = fmaf(-mean, mean, q * (1.f / 16384.f));
    float g = gam[i] * rsqrtf(var + BN_EPS);
    sc[i] = g; sh[i] = fmaf(-mean, g, bet[i]);
}

// ----------------------------- softmax/pool ---------------------------------
__global__ void __launch_bounds__(256, 1)
softmax_pts_kernel(const float* __restrict__ t3, const __half* __restrict__ h4raw,
                   const float* __restrict__ scaleL, const float* __restrict__ shiftL,
                   const float* __restrict__ aW4, const float* __restrict__ ab4,
                   float* __restrict__ out)
{
    int b = blockIdx.x, n = blockIdx.y;
    extern __shared__ float base_sh[];
    __shared__ float w4[3][64], b4[3];
    int tid = threadIdx.x;
    if (tid < 192) w4[tid / 64][tid % 64] = aW4[n * 192 + tid];
    if (tid < 3) b4[tid] = ab4[n * 3 + tid];
    const float* sc = scaleL + n * 64;
    const float* sh = shiftL + n * 64;
    const __half* h4b = h4raw + ((size_t)n * MROWS + b * 512) * 64;
    for (int i = tid; i < 512 * 64; i += 256) {
        int l = i >> 6, k = i & 63;
        base_sh[l * 65 + k] = fmaxf(fmaf(__half2float(h4b[i]), sc[k], sh[k]), 0.f);
    }
    __syncthreads();
    int lane = tid & 31, warp = tid >> 5;
    const float* t3b = t3 + ((size_t)n * MROWS + b * 512) * 128;
    float* orow = out + ((size_t)b * 2048 + n * 128) * 3;
    for (int c = 0; c < 16; c++) {
        int m = warp + c * 8;
        float v[16], mx = -1e30f;
#pragma unroll
        for (int i = 0; i < 16; i++) { v[i] = t3b[(size_t)(lane + 32*i) * 128 + m]; mx = fmaxf(mx, v[i]); }
#pragma unroll
        for (int s = 16; s > 0; s >>= 1) mx = fmaxf(mx, __shfl_xor_sync(0xffffffffu, mx, s));
        float sum = 0.f;
#pragma unroll
        for (int i = 0; i < 16; i++) { v[i] = expf(v[i] - mx); sum += v[i]; }
#pragma unroll
        for (int s = 16; s > 0; s >>= 1) sum += __shfl_xor_sync(0xffffffffu, sum, s);
        float inv = 1.f / sum;
#pragma unroll
        for (int i = 0; i < 16; i++) v[i] *= inv;
        float o0 = 0.f, o1 = 0.f, o2 = 0.f;
        for (int k = 0; k < 64; k++) {
            float p = 0.f;
#pragma unroll
            for (int i = 0; i < 16; i++) p = fmaf(v[i], base_sh[(lane + 32*i) * 65 + k], p);
#pragma unroll
            for (int s = 16; s > 0; s >>= 1) p += __shfl_xor_sync(0xffffffffu, p, s);
            o0 = fmaf(w4[0][k], p, o0); o1 = fmaf(w4[1][k], p, o1); o2 = fmaf(w4[2][k], p, o2);
        }
        if (lane == 0) { orow[m*3] = o0 + b4[0]; orow[m*3+1] = o1 + b4[1]; orow[m*3+2] = o2 + b4[2]; }
    }
}

// ------------------------------- launch ------------------------------------
extern "C" void kernel_launch(void* const* d_in, const int* in_sizes, int n_in,
                              void* d_out, int out_size)
{
    (void)in_sizes; (void)n_in; (void)out_size;
    const float* x     = (const float*)d_in[0];
    const float* xpart = (const float*)d_in[1];
    const float* mW1 = (const float*)d_in[2];
    const float* mg1 = (const float*)d_in[4];
    const float* mB1 = (const float*)d_in[5];
    const float* mW2 = (const float*)d_in[6];
    const float* mg2 = (const float*)d_in[8];
    const float* mB2 = (const float*)d_in[9];
    const float* mW3 = (const float*)d_in[10];
    const float* mg3 = (const float*)d_in[12];
    const float* mB3 = (const float*)d_in[13];
    const float* mW4 = (const float*)d_in[14];
    const float* mg4 = (const float*)d_in[16];
    const float* mB4 = (const float*)d_in[17];
    const float* aW1 = (const float*)d_in[18];
    const float* ag1 = (const float*)d_in[20];
    const float* aB1 = (const float*)d_in[21];
    const float* aW2 = (const float*)d_in[22];
    const float* ag2 = (const float*)d_in[24];
    const float* aB2 = (const float*)d_in[25];
    const float* aW3 = (const float*)d_in[26];
    const float* aW4 = (const float*)d_in[28];
    const float* ab4 = (const float*)d_in[29];
    float* out = (float*)d_out;

    __half *bufA, *bufB, *h4, *t1, *t2;
    float *t3, *psum, *psq, *sc, *sh;
    __half *Xf, *W1f, *W2f, *W3f, *W4f, *Wa1f, *Wa2f, *Wa3f;
    cudaGetSymbolAddress((void**)&bufA, g_bufA);
    cudaGetSymbolAddress((void**)&bufB, g_bufB);
    cudaGetSymbolAddress((void**)&h4, g_h4);
    cudaGetSymbolAddress((void**)&t1, g_t1);
    cudaGetSymbolAddress((void**)&t2, g_t2);
    cudaGetSymbolAddress((void**)&t3, g_t3);
    cudaGetSymbolAddress((void**)&psum, g_psum);
    cudaGetSymbolAddress((void**)&psq, g_psq);
    cudaGetSymbolAddress((void**)&sc, g_scale);
    cudaGetSymbolAddress((void**)&sh, g_shift);
    cudaGetSymbolAddress((void**)&Xf, g_Xf);
    cudaGetSymbolAddress((void**)&W1f, g_W1f);
    cudaGetSymbolAddress((void**)&W2f, g_W2f);
    cudaGetSymbolAddress((void**)&W3f, g_W3f);
    cudaGetSymbolAddress((void**)&W4f, g_W4f);
    cudaGetSymbolAddress((void**)&Wa1f, g_Wa1f);
    cudaGetSymbolAddress((void**)&Wa2f, g_Wa2f);
    cudaGetSymbolAddress((void**)&Wa3f, g_Wa3f);

    static bool init_done = false;
    static cudaStream_t s2;
    static cudaEvent_t evFork, evJoin;
    if (!init_done) {
        cudaFuncSetAttribute(softmax_pts_kernel, cudaFuncAttributeMaxDynamicSharedMemorySize, 512 * 65 * 4);
        cudaFuncSetAttribute(gemm_f16<__half, false>, cudaFuncAttributeMaxDynamicSharedMemorySize, 3 * STG);
        cudaFuncSetAttribute(gemm_f16<__half, true>,  cudaFuncAttributeMaxDynamicSharedMemorySize, 3 * STG);
        cudaFuncSetAttribute(gemm_f16<float, true>,   cudaFuncAttributeMaxDynamicSharedMemorySize, 3 * STG);
        cudaStreamCreateWithFlags(&s2, cudaStreamNonBlocking);
        cudaEventCreateWithFlags(&evFork, cudaEventDisableTiming);
        cudaEventCreateWithFlags(&evJoin, cudaEventDisableTiming);
        init_done = true;
    }

    const int SL = NBR * 512;
    const long MS512 = (long)MROWS * 512;
    const long MS64  = (long)MROWS * 64;
    const long MS128 = (long)MROWS * 128;
    const int DSM = 3 * STG;

    cudaEventRecord(evFork, 0);
    cudaStreamWaitEvent(s2, evFork, 0);
    fps_kernel<<<32 * FPS_CL, 512, 0, s2>>>(xpart, out);
    cudaEventRecord(evJoin, s2);

    conv_plain<<<(NBR*512*128)/256, 256>>>(mW1, W1f, NBR*512*128);
    conv_plain<<<(NBR*512*256)/256, 256>>>(mW2, W2f, NBR*512*256);
    conv_plain<<<(NBR*512*256)/256, 256>>>(mW3, W3f, NBR*512*256);
    conv_wpad_g<<<(NBR*128*512)/512, 256>>>(mW4, W4f, 512, 9);
    conv_wpad_g<<<(NBR*128*64)/512, 256>>>(aW1, Wa1f, 64, 6);
    conv_plain<<<(NBR*128*32)/256, 256>>>(aW2, Wa2f, NBR*128*32);
    conv_plain<<<(NBR*128*64)/256, 256>>>(aW3, Wa3f, NBR*128*64);
    conv_plain<<<(MROWS*128)/256, 256>>>(x, Xf, MROWS*128);

    gemm_f16<__half, false><<<dim3(4, 128, NBR), 256, DSM>>>(
        Xf, W1f, bufA, psum, psq, nullptr, nullptr, 256, 0, 512L*256, 512);
    bn_finalize<<<16, 256>>>(psum, psq, mg1, mB1, sc, sh, NBR * 512);

    gemm_f16<__half, true><<<dim3(4, 128, NBR), 256, DSM>>>(
        bufA, W2f, bufB, psum, psq, sc, sh, 512, MS512, 512L*512, 512);
    bn_finalize<<<16, 256>>>(psum, psq, mg2, mB2, sc + SL, sh + SL, NBR * 512);

    gemm_f16<__half, true><<<dim3(4, 128, NBR), 256, DSM>>>(
        bufB, W3f, bufA, psum, psq, sc + SL, sh + SL, 512, MS512, 512L*512, 512);
    bn_finalize<<<16, 256>>>(psum, psq, mg3, mB3, sc + 2 * SL, sh + 2 * SL, NBR * 512);

    gemm_f16<__half, true><<<dim3(1, 128, NBR), 256, DSM>>>(
        bufA, W4f, h4, psum, psq, sc + 2 * SL, sh + 2 * SL, 512, MS512, 128L*512, 64);
    bn_finalize<<<2, 256>>>(psum, psq, mg4, mB4, sc + 3 * SL, sh + 3 * SL, NBR * 64);

    gemm_f16<__half, true><<<dim3(1, 128, NBR), 256, DSM>>>(
        h4, Wa1f, t1, psum, psq, sc + 3 * SL, sh + 3 * SL, 64, MS64, 128L*64, 64);
    bn_finalize<<<2, 256>>>(psum, psq, ag1, aB1, sc + 4 * SL, sh + 4 * SL, NBR * 64);

    gemm_f16<__half, true><<<dim3(1, 128, NBR), 256, DSM>>>(
        t1, Wa2f, t2, psum, psq, sc + 4 * SL, sh + 4 * SL, 64, MS64, 128L*64, 128);
    bn_finalize<<<4, 256>>>(psum, psq, ag2, aB2, sc + 5 * SL, sh + 5 * SL, NBR * 128);

    gemm_f16<float, true><<<dim3(1, 128, NBR), 256, DSM>>>(
        t2, Wa3f, t3, psum, psq, sc + 5 * SL, sh + 5 * SL, 128, MS128, 128L*128, 128);

    softmax_pts_kernel<<<dim3(32, NBR), 256, 512 * 65 * 4>>>(
        t3, h4, sc + 3 * SL, sh + 3 * SL, aW4, ab4, out);

    cudaStreamWaitEvent(0, evJoin, 0);
}